// round 12
// baseline (speedup 1.0000x reference)
#include <cuda_runtime.h>
#include <cuda_bf16.h>
#include <cstdint>

// NLTKHierarchicalSoftmax: B=4096, NHID=512, BR=32, DEPTH=3
// Round 12: W-stationary smem for shared nodes.
//   CTAs [0,128):   level 2 — warp-per-bucket, R4 register-prefetch W (private)
//   CTAs [128,160): level 0 — node-0 W loaded once to smem (pre-paired f32x2),
//                   128 natural-order samples per CTA
//   CTAs [160,192): level 1 — node (1+k) W to smem; samples from sorted range
//                   [g_off[32k], g_off[32k+32])
// Sort (batched counting) + last-CTA fused product as in R10.

#define FULL 0xffffffffu
#define NHID 512
#define BR 32
#define NB2 1024
#define BTOT 4096
#define WNODE (NHID*BR)
#define NCTA 192
#define WPAIRS 8192                    // 256 h-pairs x 32 cols
// dynamic smem: wpair (64KB) + xs_tile 8 warps x 8 x 128 floats (32KB)
#define DSMEM_BYTES (WPAIRS * 8 + 8 * 8 * 128 * 4)

__device__ int g_off[NB2 + 1];
__device__ int g_sorted[BTOT];
__device__ float g_p[3 * BTOT];
__device__ int g_done;                 // zero-init; reset by last CTA

typedef unsigned long long u64t;

__device__ __forceinline__ u64t ffma2(u64t a, u64t b, u64t c)
{
    u64t d;
    asm("fma.rn.f32x2 %0, %1, %2, %3;" : "=l"(d) : "l"(a), "l"(b), "l"(c));
    return d;
}
__device__ __forceinline__ u64t packf2(float lo, float hi)
{
    u64t d;
    asm("mov.b64 %0, {%1, %2};" : "=l"(d) : "f"(lo), "f"(hi));
    return d;
}
__device__ __forceinline__ float2 unpackf2(u64t v)
{
    float2 r;
    asm("mov.b64 {%0, %1}, %2;" : "=f"(r.x), "=f"(r.y) : "l"(v));
    return r;
}

// ---------------- counting sort (single CTA, 1024 thr, batched loads) ---------
__global__ void __launch_bounds__(NB2) k_sort(const int* __restrict__ labels, int B)
{
    __shared__ int cnt[NB2];
    __shared__ int cur[NB2];
    __shared__ int wsum[32];
    int t = threadIdx.x;
    int lane = t & 31;
    int warp = t >> 5;

    cnt[t] = 0;
    __syncthreads();

    int l0 = (t        < B) ? __ldg(&labels[t])        : -1;
    int l1 = (t + 1024 < B) ? __ldg(&labels[t + 1024]) : -1;
    int l2 = (t + 2048 < B) ? __ldg(&labels[t + 2048]) : -1;
    int l3 = (t + 3072 < B) ? __ldg(&labels[t + 3072]) : -1;
    if (l0 >= 0) atomicAdd(&cnt[l0 >> 5], 1);
    if (l1 >= 0) atomicAdd(&cnt[l1 >> 5], 1);
    if (l2 >= 0) atomicAdd(&cnt[l2 >> 5], 1);
    if (l3 >= 0) atomicAdd(&cnt[l3 >> 5], 1);
    __syncthreads();

    int v = cnt[t];
    int inc = v;
    #pragma unroll
    for (int o = 1; o < 32; o <<= 1) {
        int u = __shfl_up_sync(FULL, inc, o);
        if (lane >= o) inc += u;
    }
    if (lane == 31) wsum[warp] = inc;
    __syncthreads();
    if (t < 32) {
        int wv = wsum[t];
        int wi = wv;
        #pragma unroll
        for (int o = 1; o < 32; o <<= 1) {
            int u = __shfl_up_sync(FULL, wi, o);
            if (t >= o) wi += u;
        }
        wsum[t] = wi - wv;
    }
    __syncthreads();

    int excl = wsum[warp] + inc - v;
    g_off[t] = excl;
    cur[t] = excl;
    if (t == NB2 - 1) g_off[NB2] = excl + v;
    __syncthreads();

    if (l0 >= 0) g_sorted[atomicAdd(&cur[l0 >> 5], 1)] = t;
    if (l1 >= 0) g_sorted[atomicAdd(&cur[l1 >> 5], 1)] = t + 1024;
    if (l2 >= 0) g_sorted[atomicAdd(&cur[l2 >> 5], 1)] = t + 2048;
    if (l3 >= 0) g_sorted[atomicAdd(&cur[l3 >> 5], 1)] = t + 3072;
}

// ---------------- shared softmax/emit -----------------------------------------
template<int TS>
__device__ __forceinline__ void softmax_emit(
    u64t* acc2, unsigned msk, const int* bs, const int* step,
    int lane, float* __restrict__ pout)
{
    #pragma unroll
    for (int s = 0; s < TS; s++) {
        if (msk & (1u << s)) {
            float2 h = unpackf2(acc2[s]);
            float acc = h.x + h.y;
            float m = acc;
            #pragma unroll
            for (int o = 16; o > 0; o >>= 1)
                m = fmaxf(m, __shfl_xor_sync(FULL, m, o));
            float e = __expf(acc - m);
            float sum = e;
            #pragma unroll
            for (int o = 16; o > 0; o >>= 1)
                sum += __shfl_xor_sync(FULL, sum, o);
            float est = __shfl_sync(FULL, e, step[s]);
            if (lane == 0) pout[bs[s]] = est / sum;
        }
    }
    __syncwarp();
}

// ---------------- R4 register-prefetch run (level 2) --------------------------
template<int TS>
__device__ __forceinline__ void process_run_reg(
    const float* __restrict__ x, const float* __restrict__ Wn,
    const int* bs, unsigned msk, const int* step,
    int lane, float (*xsm)[128], float* __restrict__ pout)
{
    u64t acc2[TS];
    #pragma unroll
    for (int s = 0; s < TS; s++) acc2[s] = 0ull;

    float wr[2][16];
    #pragma unroll
    for (int k = 0; k < 16; k++)
        wr[0][k] = __ldg(Wn + k * BR + lane);

    #pragma unroll 1
    for (int sc = 0; sc < 4; sc++) {
        __syncwarp();
        #pragma unroll
        for (int s = 0; s < TS; s++) {
            float4 xv = *(const float4*)(x + (size_t)bs[s] * NHID
                                         + sc * 128 + lane * 4);
            *(float4*)&xsm[s][lane * 4] = xv;
        }
        __syncwarp();

        #pragma unroll
        for (int sub = 0; sub < 8; sub++) {
            const int curb = sub & 1;
            const int subg = sc * 8 + sub;
            if (subg + 1 < 32) {
                int h0 = (subg + 1) * 16;
                #pragma unroll
                for (int k = 0; k < 16; k++)
                    wr[curb ^ 1][k] = __ldg(Wn + (h0 + k) * BR + lane);
            }
            u64t wp[8];
            #pragma unroll
            for (int k = 0; k < 8; k++)
                wp[k] = packf2(wr[curb][2 * k], wr[curb][2 * k + 1]);

            #pragma unroll
            for (int q = 0; q < 4; q++) {
                #pragma unroll
                for (int s = 0; s < TS; s++) {
                    ulonglong2 xq =
                        *(const ulonglong2*)&xsm[s][sub * 16 + q * 4];
                    acc2[s] = ffma2(xq.x, wp[2 * q], acc2[s]);
                    acc2[s] = ffma2(xq.y, wp[2 * q + 1], acc2[s]);
                }
            }
        }
    }
    softmax_emit<TS>(acc2, msk, bs, step, lane, pout);
}

// ---------------- W-stationary smem run (levels 0/1) --------------------------
// wps: node W pre-paired in smem, wps[(pair)*32 + lane] = {W[2p][c], W[2p+1][c]}
template<int TS>
__device__ __forceinline__ void process_run_smem(
    const float* __restrict__ x, const u64t* __restrict__ wps,
    const int* bs, unsigned msk, const int* step,
    int lane, float (*xsm)[128], float* __restrict__ pout)
{
    u64t acc2[TS];
    #pragma unroll
    for (int s = 0; s < TS; s++) acc2[s] = 0ull;

    #pragma unroll 1
    for (int sc = 0; sc < 4; sc++) {
        __syncwarp();
        #pragma unroll
        for (int s = 0; s < TS; s++) {
            float4 xv = *(const float4*)(x + (size_t)bs[s] * NHID
                                         + sc * 128 + lane * 4);
            *(float4*)&xsm[s][lane * 4] = xv;
        }
        __syncwarp();

        #pragma unroll
        for (int sub = 0; sub < 8; sub++) {
            u64t wp[8];
            #pragma unroll
            for (int k = 0; k < 8; k++)
                wp[k] = wps[(sc * 64 + sub * 8 + k) * 32 + lane];  // LDS.64

            #pragma unroll
            for (int q = 0; q < 4; q++) {
                #pragma unroll
                for (int s = 0; s < TS; s++) {
                    ulonglong2 xq =
                        *(const ulonglong2*)&xsm[s][sub * 16 + q * 4];
                    acc2[s] = ffma2(xq.x, wp[2 * q], acc2[s]);
                    acc2[s] = ffma2(xq.y, wp[2 * q + 1], acc2[s]);
                }
            }
        }
    }
    softmax_emit<TS>(acc2, msk, bs, step, lane, pout);
}

// ---------------- work kernel --------------------------------------------------
__global__ void __launch_bounds__(256, 2) k_work(
    const float* __restrict__ x, const int* __restrict__ labels,
    const float* __restrict__ W, float* __restrict__ out, int B)
{
    extern __shared__ __align__(16) u64t dyn[];
    u64t* wps = dyn;                                               // 64KB
    float (*xs_all)[8][128] = reinterpret_cast<float (*)[8][128]>(dyn + WPAIRS);
    __shared__ int s_last;

    const int tid = threadIdx.x;
    const int lane = tid & 31;
    const int wid = tid >> 5;
    const int c = blockIdx.x;
    float (*xsm)[128] = xs_all[wid];

    if (c < 128) {
        // ------------- level 2: warp-per-bucket, R4 register path -------------
        int b = c * 8 + wid;
        int beg = __ldg(&g_off[b]);
        int end = __ldg(&g_off[b + 1]);
        const float* Wn = W + (size_t)(33 + b) * WNODE;

        int t = beg;
        while (end - t >= 5) {
            int G = min(8, end - t);
            int bs[8], step[8];
            #pragma unroll
            for (int s = 0; s < 8; s++) {
                int idx = t + ((s < G) ? s : (G - 1));
                int bb = __ldg(&g_sorted[idx]);
                bs[s] = bb;
                step[s] = __ldg(&labels[bb]) & 31;
            }
            unsigned msk = (G >= 8) ? 0xffu : ((1u << G) - 1u);
            process_run_reg<8>(x, Wn, bs, msk, step, lane, xsm, g_p + 2 * BTOT);
            t += G;
        }
        if (t < end) {
            int G = end - t;
            int bs[4], step[4];
            #pragma unroll
            for (int s = 0; s < 4; s++) {
                int idx = t + ((s < G) ? s : (G - 1));
                int bb = __ldg(&g_sorted[idx]);
                bs[s] = bb;
                step[s] = __ldg(&labels[bb]) & 31;
            }
            process_run_reg<4>(x, Wn, bs, (1u << G) - 1u, step, lane, xsm,
                               g_p + 2 * BTOT);
        }
    } else {
        // ------------- levels 0/1: W-stationary smem --------------------------
        const float* Wn = (c < 160) ? W
                                    : W + (size_t)(1 + (c - 160)) * WNODE;

        // load node W once, pre-paired into f32x2 entries (coalesced LDGs)
        #pragma unroll 4
        for (int idx = tid; idx < WPAIRS; idx += 256) {
            int p = idx >> 5, col = idx & 31;
            float a  = __ldg(Wn + (2 * p)     * BR + col);
            float bb = __ldg(Wn + (2 * p + 1) * BR + col);
            wps[idx] = packf2(a, bb);
        }
        __syncthreads();

        if (c < 160) {
            // level 0: natural order, 128 samples per CTA, 2 runs per warp
            int c0 = c - 128;
            #pragma unroll 1
            for (int r = 0; r < 2; r++) {
                int s0 = c0 * 128 + r * 64 + wid * 8;
                int bs[8], step[8];
                unsigned msk = 0;
                #pragma unroll
                for (int s = 0; s < 8; s++) {
                    int bb = min(s0 + s, B - 1);
                    bs[s] = bb;
                    step[s] = (__ldg(&labels[bb]) >> 10) & 31;
                    if (s0 + s < B) msk |= 1u << s;
                }
                process_run_smem<8>(x, wps, bs, msk, step, lane, xsm, g_p);
            }
        } else {
            // level 1: node k = c-160; sorted range [g_off[32k], g_off[32k+32))
            int k = c - 160;
            int beg = __ldg(&g_off[k * 32]);
            int end = __ldg(&g_off[k * 32 + 32]);
            int n = end - beg;
            int ntiles = (n + 7) >> 3;
            #pragma unroll 1
            for (int t = wid; t < ntiles; t += 8) {
                int t0 = beg + t * 8;
                int G = min(8, end - t0);
                int bs[8], step[8];
                #pragma unroll
                for (int s = 0; s < 8; s++) {
                    int idx = t0 + ((s < G) ? s : (G - 1));
                    int bb = __ldg(&g_sorted[idx]);
                    bs[s] = bb;
                    step[s] = (__ldg(&labels[bb]) >> 5) & 31;
                }
                unsigned msk = (G >= 8) ? 0xffu : ((1u << G) - 1u);
                process_run_smem<8>(x, wps, bs, msk, step, lane, xsm,
                                    g_p + BTOT);
            }
        }
    }

    // completion: last CTA computes the 3-factor product
    __syncthreads();
    __threadfence();
    if (tid == 0) {
        int old = atomicAdd(&g_done, 1);
        s_last = (old == NCTA - 1) ? 1 : 0;
    }
    __syncthreads();
    if (s_last) {
        __threadfence();
        for (int i = tid; i < B; i += 256)
            out[i] = g_p[i] * g_p[BTOT + i] * g_p[2 * BTOT + i];
        if (tid == 0) g_done = 0;   // reset for next graph replay
    }
}

extern "C" void kernel_launch(void* const* d_in, const int* in_sizes, int n_in,
                              void* d_out, int out_size)
{
    const float* x      = (const float*)d_in[0];
    const int*   labels = (const int*)d_in[1];
    const float* W      = (const float*)d_in[2];
    float* out = (float*)d_out;

    int B = in_sizes[1];  // 4096

    k_sort<<<1, NB2>>>(labels, B);

    cudaFuncSetAttribute(k_work, cudaFuncAttributeMaxDynamicSharedMemorySize,
                         DSMEM_BYTES);
    k_work<<<NCTA, 256, DSMEM_BYTES>>>(x, labels, W, out, B);
}

// round 13
// speedup vs baseline: 1.3824x; 1.3824x over previous
#include <cuda_runtime.h>
#include <cuda_bf16.h>
#include <cstdint>

// NLTKHierarchicalSoftmax: B=4096, NHID=512, BR=32, DEPTH=3
// Round 13: R4 structure verbatim (best measured: sort -> work -> final),
// with (a) batched counting sort, (b) k_work forced to 3 CTAs/SM via
// __launch_bounds__(256,3) plus register diet (steps packed in one u64).
// GEMV inner loop identical to R4.

#define FULL 0xffffffffu
#define NHID 512
#define BR 32
#define NB2 1024
#define BTOT 4096
#define WNODE (NHID*BR)
#define NL0 512
#define NL1 512
#define WARPS_PER_CTA 8
#define NCTA 256

__device__ int g_off[NB2 + 1];
__device__ int g_sorted[BTOT];
__device__ float g_p[3 * BTOT];

typedef unsigned long long u64t;

__device__ __forceinline__ u64t ffma2(u64t a, u64t b, u64t c)
{
    u64t d;
    asm("fma.rn.f32x2 %0, %1, %2, %3;" : "=l"(d) : "l"(a), "l"(b), "l"(c));
    return d;
}
__device__ __forceinline__ u64t packf2(float lo, float hi)
{
    u64t d;
    asm("mov.b64 %0, {%1, %2};" : "=l"(d) : "f"(lo), "f"(hi));
    return d;
}
__device__ __forceinline__ float2 unpackf2(u64t v)
{
    float2 r;
    asm("mov.b64 {%0, %1}, %2;" : "=f"(r.x), "=f"(r.y) : "l"(v));
    return r;
}

// ---------------- counting sort (single CTA, 1024 thr, batched loads) ---------
__global__ void __launch_bounds__(NB2) k_sort(const int* __restrict__ labels, int B)
{
    __shared__ int cnt[NB2];
    __shared__ int cur[NB2];
    __shared__ int wsum[32];
    int t = threadIdx.x;
    int lane = t & 31;
    int warp = t >> 5;

    cnt[t] = 0;
    __syncthreads();

    int l0 = (t        < B) ? __ldg(&labels[t])        : -1;
    int l1 = (t + 1024 < B) ? __ldg(&labels[t + 1024]) : -1;
    int l2 = (t + 2048 < B) ? __ldg(&labels[t + 2048]) : -1;
    int l3 = (t + 3072 < B) ? __ldg(&labels[t + 3072]) : -1;
    if (l0 >= 0) atomicAdd(&cnt[l0 >> 5], 1);
    if (l1 >= 0) atomicAdd(&cnt[l1 >> 5], 1);
    if (l2 >= 0) atomicAdd(&cnt[l2 >> 5], 1);
    if (l3 >= 0) atomicAdd(&cnt[l3 >> 5], 1);
    __syncthreads();

    int v = cnt[t];
    int inc = v;
    #pragma unroll
    for (int o = 1; o < 32; o <<= 1) {
        int u = __shfl_up_sync(FULL, inc, o);
        if (lane >= o) inc += u;
    }
    if (lane == 31) wsum[warp] = inc;
    __syncthreads();
    if (t < 32) {
        int wv = wsum[t];
        int wi = wv;
        #pragma unroll
        for (int o = 1; o < 32; o <<= 1) {
            int u = __shfl_up_sync(FULL, wi, o);
            if (t >= o) wi += u;
        }
        wsum[t] = wi - wv;
    }
    __syncthreads();

    int excl = wsum[warp] + inc - v;
    g_off[t] = excl;
    cur[t] = excl;
    if (t == NB2 - 1) g_off[NB2] = excl + v;
    __syncthreads();

    if (l0 >= 0) g_sorted[atomicAdd(&cur[l0 >> 5], 1)] = t;
    if (l1 >= 0) g_sorted[atomicAdd(&cur[l1 >> 5], 1)] = t + 1024;
    if (l2 >= 0) g_sorted[atomicAdd(&cur[l2 >> 5], 1)] = t + 2048;
    if (l3 >= 0) g_sorted[atomicAdd(&cur[l3 >> 5], 1)] = t + 3072;
}

// ---------------- pipelined run processor (R4 core; steps packed) -------------
// stepp: packed step values, 5 bits per sample (s*5 .. s*5+4)
template<int TS>
__device__ __forceinline__ void process_run(
    const float* __restrict__ x, const float* __restrict__ Wn,
    const int* bs, unsigned msk, u64t stepp,
    int lane, float (*xsm)[128], float* __restrict__ pout)
{
    u64t acc2[TS];
    #pragma unroll
    for (int s = 0; s < TS; s++) acc2[s] = 0ull;

    float wr[2][16];
    #pragma unroll
    for (int k = 0; k < 16; k++)
        wr[0][k] = __ldg(Wn + k * BR + lane);

    #pragma unroll 1
    for (int sc = 0; sc < 4; sc++) {            // 4 superchunks of 128 h
        __syncwarp();
        #pragma unroll
        for (int s = 0; s < TS; s++) {
            float4 xv = *(const float4*)(x + (size_t)bs[s] * NHID
                                         + sc * 128 + lane * 4);
            *(float4*)&xsm[s][lane * 4] = xv;
        }
        __syncwarp();

        #pragma unroll
        for (int sub = 0; sub < 8; sub++) {     // 8 subchunks of 16 h
            const int curb = sub & 1;
            const int subg = sc * 8 + sub;
            if (subg + 1 < 32) {                // prefetch next subchunk W
                int h0 = (subg + 1) * 16;
                #pragma unroll
                for (int k = 0; k < 16; k++)
                    wr[curb ^ 1][k] = __ldg(Wn + (h0 + k) * BR + lane);
            }
            u64t wp[8];
            #pragma unroll
            for (int k = 0; k < 8; k++)
                wp[k] = packf2(wr[curb][2 * k], wr[curb][2 * k + 1]);

            #pragma unroll
            for (int q = 0; q < 4; q++) {
                #pragma unroll
                for (int s = 0; s < TS; s++) {  // independent acc chains
                    ulonglong2 xq =
                        *(const ulonglong2*)&xsm[s][sub * 16 + q * 4];
                    acc2[s] = ffma2(xq.x, wp[2 * q], acc2[s]);
                    acc2[s] = ffma2(xq.y, wp[2 * q + 1], acc2[s]);
                }
            }
        }
    }

    // per-sample warp softmax over 32 columns (lane = column)
    #pragma unroll
    for (int s = 0; s < TS; s++) {
        if (msk & (1u << s)) {
            float2 h = unpackf2(acc2[s]);
            float acc = h.x + h.y;
            float m = acc;
            #pragma unroll
            for (int o = 16; o > 0; o >>= 1)
                m = fmaxf(m, __shfl_xor_sync(FULL, m, o));
            float e = __expf(acc - m);
            float sum = e;
            #pragma unroll
            for (int o = 16; o > 0; o >>= 1)
                sum += __shfl_xor_sync(FULL, sum, o);
            int st = (int)((stepp >> (5 * s)) & 31);
            float est = __shfl_sync(FULL, e, st);
            if (lane == 0) pout[bs[s]] = est / sum;
        }
    }
    __syncwarp();
}

// ---------------- work kernel (3 CTAs/SM target) ------------------------------
__global__ void __launch_bounds__(32 * WARPS_PER_CTA, 3) k_work(
    const float* __restrict__ x, const int* __restrict__ labels,
    const float* __restrict__ W, int B)
{
    __shared__ __align__(16) float xs_tile[WARPS_PER_CTA][8][128];

    const int lane = threadIdx.x & 31;
    const int wid = threadIdx.x >> 5;
    int gw = blockIdx.x * WARPS_PER_CTA + wid;
    float (*xsm)[128] = xs_tile[wid];

    if (gw < NL0) {
        // level 0: node 0, natural order (no sort dependency)
        int s0 = gw * 8;
        int bs[8];
        u64t stepp = 0;
        unsigned msk = 0;
        #pragma unroll
        for (int s = 0; s < 8; s++) {
            int b = min(s0 + s, B - 1);
            bs[s] = b;
            stepp |= (u64t)((__ldg(&labels[b]) >> 10) & 31) << (5 * s);
            if (s0 + s < B) msk |= 1u << s;
        }
        process_run<8>(x, W, bs, msk, stepp, lane, xsm, g_p);
    } else if (gw < NL0 + NL1) {
        // level 1: tiles of 8 consecutive sorted samples; node = 1 + (lab>>10)
        int s0 = (gw - NL0) * 8;
        int bs[8];
        u64t stepp = 0;
        unsigned node8 = 0;            // 5-bit node keys packed in a u64 below
        u64t nodep = 0;
        #pragma unroll
        for (int s = 0; s < 8; s++) {
            int idx = min(s0 + s, B - 1);
            int b = __ldg(&g_sorted[idx]);
            bs[s] = b;
            int lab = __ldg(&labels[b]);
            nodep |= (u64t)(lab >> 10) << (5 * s);
            stepp |= (u64t)((lab >> 5) & 31) << (5 * s);
        }
        (void)node8;
        unsigned valid = (s0 + 8 <= B) ? 0xffu : ((1u << (B - s0)) - 1u);
        unsigned rem = valid;
        while (rem) {
            int src = __ffs(rem) - 1;
            int n = (int)((nodep >> (5 * src)) & 31);
            unsigned msk = 0;
            #pragma unroll
            for (int s = 0; s < 8; s++)
                if ((int)((nodep >> (5 * s)) & 31) == n) msk |= 1u << s;
            msk &= valid;
            process_run<8>(x, W + (size_t)(1 + n) * WNODE, bs, msk, stepp,
                           lane, xsm, g_p + BTOT);
            rem &= ~msk;
        }
    } else if (gw < NL0 + NL1 + NB2) {
        // level 2: one warp per bucket (node = 33 + bucket)
        int w = gw - NL0 - NL1;
        int beg = __ldg(&g_off[w]);
        int end = __ldg(&g_off[w + 1]);
        const float* Wn = W + (size_t)(33 + w) * WNODE;

        int t = beg;
        while (end - t >= 5) {
            int G = min(8, end - t);
            int bs[8];
            u64t stepp = 0;
            #pragma unroll
            for (int s = 0; s < 8; s++) {
                int idx = t + ((s < G) ? s : (G - 1));
                int b = __ldg(&g_sorted[idx]);
                bs[s] = b;
                stepp |= (u64t)(__ldg(&labels[b]) & 31) << (5 * s);
            }
            unsigned msk = (G >= 8) ? 0xffu : ((1u << G) - 1u);
            process_run<8>(x, Wn, bs, msk, stepp, lane, xsm, g_p + 2 * BTOT);
            t += G;
        }
        if (t < end) {
            int G = end - t;
            int bs[4];
            u64t stepp = 0;
            #pragma unroll
            for (int s = 0; s < 4; s++) {
                int idx = t + ((s < G) ? s : (G - 1));
                int b = __ldg(&g_sorted[idx]);
                bs[s] = b;
                stepp |= (u64t)(__ldg(&labels[b]) & 31) << (5 * s);
            }
            process_run<4>(x, Wn, bs, (1u << G) - 1u, stepp, lane, xsm,
                           g_p + 2 * BTOT);
        }
    }
}

__global__ void k_final(float* __restrict__ out, int B)
{
    int i = blockIdx.x * blockDim.x + threadIdx.x;
    if (i < B) out[i] = g_p[i] * g_p[BTOT + i] * g_p[2 * BTOT + i];
}

extern "C" void kernel_launch(void* const* d_in, const int* in_sizes, int n_in,
                              void* d_out, int out_size)
{
    const float* x      = (const float*)d_in[0];
    const int*   labels = (const int*)d_in[1];
    const float* W      = (const float*)d_in[2];
    float* out = (float*)d_out;

    int B = in_sizes[1];  // 4096

    k_sort<<<1, NB2>>>(labels, B);
    k_work<<<NCTA, 256>>>(x, labels, W, B);
    k_final<<<(B + 255) / 256, 256>>>(out, B);
}

// round 14
// speedup vs baseline: 1.6257x; 1.1760x over previous
#include <cuda_runtime.h>
#include <cuda_bf16.h>
#include <cstdint>

// NLTKHierarchicalSoftmax: B=4096, NHID=512, BR=32, DEPTH=3
// Round 14: W-stationary smem for L0/L1 with the R4 grid shape (256 CTAs).
//   bids [0,128):   level 2 — warp-per-bucket, R4 register-prefetch path
//   bids [128,192): level 0 — 64 samples/CTA, node-0 W in smem (f32x2-paired)
//   bids [192,256): level 1 — 2 CTAs per node (even/odd tiles of the node's
//                   sorted range), node W in smem
// sort -> work -> final, as in R4.

#define FULL 0xffffffffu
#define NHID 512
#define BR 32
#define NB2 1024
#define BTOT 4096
#define WNODE (NHID*BR)
#define NCTA 256
#define WPAIRS 8192                    // 256 h-pairs x 32 cols
// dynamic smem: wps (64KB) + xs_tile 8 warps x 8 x 128 floats (32KB)
#define DSMEM_BYTES (WPAIRS * 8 + 8 * 8 * 128 * 4)

__device__ int g_off[NB2 + 1];
__device__ int g_sorted[BTOT];
__device__ float g_p[3 * BTOT];

typedef unsigned long long u64t;

__device__ __forceinline__ u64t ffma2(u64t a, u64t b, u64t c)
{
    u64t d;
    asm("fma.rn.f32x2 %0, %1, %2, %3;" : "=l"(d) : "l"(a), "l"(b), "l"(c));
    return d;
}
__device__ __forceinline__ u64t packf2(float lo, float hi)
{
    u64t d;
    asm("mov.b64 %0, {%1, %2};" : "=l"(d) : "f"(lo), "f"(hi));
    return d;
}
__device__ __forceinline__ float2 unpackf2(u64t v)
{
    float2 r;
    asm("mov.b64 {%0, %1}, %2;" : "=f"(r.x), "=f"(r.y) : "l"(v));
    return r;
}

// ---------------- counting sort (single CTA, 1024 thr, batched loads) ---------
__global__ void __launch_bounds__(NB2) k_sort(const int* __restrict__ labels, int B)
{
    __shared__ int cnt[NB2];
    __shared__ int cur[NB2];
    __shared__ int wsum[32];
    int t = threadIdx.x;
    int lane = t & 31;
    int warp = t >> 5;

    cnt[t] = 0;
    __syncthreads();

    int l0 = (t        < B) ? __ldg(&labels[t])        : -1;
    int l1 = (t + 1024 < B) ? __ldg(&labels[t + 1024]) : -1;
    int l2 = (t + 2048 < B) ? __ldg(&labels[t + 2048]) : -1;
    int l3 = (t + 3072 < B) ? __ldg(&labels[t + 3072]) : -1;
    if (l0 >= 0) atomicAdd(&cnt[l0 >> 5], 1);
    if (l1 >= 0) atomicAdd(&cnt[l1 >> 5], 1);
    if (l2 >= 0) atomicAdd(&cnt[l2 >> 5], 1);
    if (l3 >= 0) atomicAdd(&cnt[l3 >> 5], 1);
    __syncthreads();

    int v = cnt[t];
    int inc = v;
    #pragma unroll
    for (int o = 1; o < 32; o <<= 1) {
        int u = __shfl_up_sync(FULL, inc, o);
        if (lane >= o) inc += u;
    }
    if (lane == 31) wsum[warp] = inc;
    __syncthreads();
    if (t < 32) {
        int wv = wsum[t];
        int wi = wv;
        #pragma unroll
        for (int o = 1; o < 32; o <<= 1) {
            int u = __shfl_up_sync(FULL, wi, o);
            if (t >= o) wi += u;
        }
        wsum[t] = wi - wv;
    }
    __syncthreads();

    int excl = wsum[warp] + inc - v;
    g_off[t] = excl;
    cur[t] = excl;
    if (t == NB2 - 1) g_off[NB2] = excl + v;
    __syncthreads();

    if (l0 >= 0) g_sorted[atomicAdd(&cur[l0 >> 5], 1)] = t;
    if (l1 >= 0) g_sorted[atomicAdd(&cur[l1 >> 5], 1)] = t + 1024;
    if (l2 >= 0) g_sorted[atomicAdd(&cur[l2 >> 5], 1)] = t + 2048;
    if (l3 >= 0) g_sorted[atomicAdd(&cur[l3 >> 5], 1)] = t + 3072;
}

// ---------------- shared softmax/emit -----------------------------------------
template<int TS>
__device__ __forceinline__ void softmax_emit(
    u64t* acc2, unsigned msk, const int* bs, const int* step,
    int lane, float* __restrict__ pout)
{
    #pragma unroll
    for (int s = 0; s < TS; s++) {
        if (msk & (1u << s)) {
            float2 h = unpackf2(acc2[s]);
            float acc = h.x + h.y;
            float m = acc;
            #pragma unroll
            for (int o = 16; o > 0; o >>= 1)
                m = fmaxf(m, __shfl_xor_sync(FULL, m, o));
            float e = __expf(acc - m);
            float sum = e;
            #pragma unroll
            for (int o = 16; o > 0; o >>= 1)
                sum += __shfl_xor_sync(FULL, sum, o);
            float est = __shfl_sync(FULL, e, step[s]);
            if (lane == 0) pout[bs[s]] = est / sum;
        }
    }
    __syncwarp();
}

// ---------------- R4 register-prefetch run (level 2) --------------------------
template<int TS>
__device__ __forceinline__ void process_run_reg(
    const float* __restrict__ x, const float* __restrict__ Wn,
    const int* bs, unsigned msk, const int* step,
    int lane, float (*xsm)[128], float* __restrict__ pout)
{
    u64t acc2[TS];
    #pragma unroll
    for (int s = 0; s < TS; s++) acc2[s] = 0ull;

    float wr[2][16];
    #pragma unroll
    for (int k = 0; k < 16; k++)
        wr[0][k] = __ldg(Wn + k * BR + lane);

    #pragma unroll 1
    for (int sc = 0; sc < 4; sc++) {
        __syncwarp();
        #pragma unroll
        for (int s = 0; s < TS; s++) {
            float4 xv = *(const float4*)(x + (size_t)bs[s] * NHID
                                         + sc * 128 + lane * 4);
            *(float4*)&xsm[s][lane * 4] = xv;
        }
        __syncwarp();

        #pragma unroll
        for (int sub = 0; sub < 8; sub++) {
            const int curb = sub & 1;
            const int subg = sc * 8 + sub;
            if (subg + 1 < 32) {
                int h0 = (subg + 1) * 16;
                #pragma unroll
                for (int k = 0; k < 16; k++)
                    wr[curb ^ 1][k] = __ldg(Wn + (h0 + k) * BR + lane);
            }
            u64t wp[8];
            #pragma unroll
            for (int k = 0; k < 8; k++)
                wp[k] = packf2(wr[curb][2 * k], wr[curb][2 * k + 1]);

            #pragma unroll
            for (int q = 0; q < 4; q++) {
                #pragma unroll
                for (int s = 0; s < TS; s++) {
                    ulonglong2 xq =
                        *(const ulonglong2*)&xsm[s][sub * 16 + q * 4];
                    acc2[s] = ffma2(xq.x, wp[2 * q], acc2[s]);
                    acc2[s] = ffma2(xq.y, wp[2 * q + 1], acc2[s]);
                }
            }
        }
    }
    softmax_emit<TS>(acc2, msk, bs, step, lane, pout);
}

// ---------------- W-stationary smem run (levels 0/1) --------------------------
// wps[(pair)*32 + lane] = {W[2p][lane], W[2p+1][lane]} as f32x2
__device__ __forceinline__ void process_run_smem(
    const float* __restrict__ x, const u64t* __restrict__ wps,
    const int* bs, unsigned msk, const int* step,
    int lane, float (*xsm)[128], float* __restrict__ pout)
{
    u64t acc2[8];
    #pragma unroll
    for (int s = 0; s < 8; s++) acc2[s] = 0ull;

    #pragma unroll 1
    for (int sc = 0; sc < 4; sc++) {
        __syncwarp();
        #pragma unroll
        for (int s = 0; s < 8; s++) {
            float4 xv = *(const float4*)(x + (size_t)bs[s] * NHID
                                         + sc * 128 + lane * 4);
            *(float4*)&xsm[s][lane * 4] = xv;
        }
        __syncwarp();

        #pragma unroll
        for (int sub = 0; sub < 8; sub++) {
            u64t wp[8];
            #pragma unroll
            for (int k = 0; k < 8; k++)
                wp[k] = wps[(sc * 64 + sub * 8 + k) * 32 + lane];  // LDS.64

            #pragma unroll
            for (int q = 0; q < 4; q++) {
                #pragma unroll
                for (int s = 0; s < 8; s++) {
                    ulonglong2 xq =
                        *(const ulonglong2*)&xsm[s][sub * 16 + q * 4];
                    acc2[s] = ffma2(xq.x, wp[2 * q], acc2[s]);
                    acc2[s] = ffma2(xq.y, wp[2 * q + 1], acc2[s]);
                }
            }
        }
    }
    softmax_emit<8>(acc2, msk, bs, step, lane, pout);
}

// ---------------- work kernel --------------------------------------------------
__global__ void __launch_bounds__(256, 2) k_work(
    const float* __restrict__ x, const int* __restrict__ labels,
    const float* __restrict__ W, int B)
{
    extern __shared__ __align__(16) u64t dyn[];
    u64t* wps = dyn;                                               // 64KB
    float (*xs_all)[8][128] = reinterpret_cast<float (*)[8][128]>(dyn + WPAIRS);

    const int tid = threadIdx.x;
    const int lane = tid & 31;
    const int wid = tid >> 5;
    const int c = blockIdx.x;
    float (*xsm)[128] = xs_all[wid];

    if (c < 128) {
        // ------------- level 2: warp-per-bucket, R4 register path -------------
        int b = c * 8 + wid;
        int beg = __ldg(&g_off[b]);
        int end = __ldg(&g_off[b + 1]);
        const float* Wn = W + (size_t)(33 + b) * WNODE;

        int t = beg;
        while (end - t >= 5) {
            int G = min(8, end - t);
            int bs[8], step[8];
            #pragma unroll
            for (int s = 0; s < 8; s++) {
                int idx = t + ((s < G) ? s : (G - 1));
                int bb = __ldg(&g_sorted[idx]);
                bs[s] = bb;
                step[s] = __ldg(&labels[bb]) & 31;
            }
            unsigned msk = (G >= 8) ? 0xffu : ((1u << G) - 1u);
            process_run_reg<8>(x, Wn, bs, msk, step, lane, xsm, g_p + 2 * BTOT);
            t += G;
        }
        if (t < end) {
            int G = end - t;
            int bs[4], step[4];
            #pragma unroll
            for (int s = 0; s < 4; s++) {
                int idx = t + ((s < G) ? s : (G - 1));
                int bb = __ldg(&g_sorted[idx]);
                bs[s] = bb;
                step[s] = __ldg(&labels[bb]) & 31;
            }
            process_run_reg<4>(x, Wn, bs, (1u << G) - 1u, step, lane, xsm,
                               g_p + 2 * BTOT);
        }
    } else {
        // ------------- levels 0/1: W-stationary smem --------------------------
        const bool is_l0 = (c < 192);
        const int k = is_l0 ? 0 : ((c - 192) >> 1);     // node within level
        const float* Wn = is_l0 ? W : W + (size_t)(1 + k) * WNODE;

        // load node W once, pre-paired into f32x2 entries (coalesced LDGs)
        #pragma unroll 4
        for (int idx = tid; idx < WPAIRS; idx += 256) {
            int p = idx >> 5, col = idx & 31;
            float a  = __ldg(Wn + (2 * p)     * BR + col);
            float bb = __ldg(Wn + (2 * p + 1) * BR + col);
            wps[idx] = packf2(a, bb);
        }
        __syncthreads();

        if (is_l0) {
            // level 0: natural order, 64 samples/CTA, one run per warp
            int s0 = (c - 128) * 64 + wid * 8;
            int bs[8], step[8];
            unsigned msk = 0;
            #pragma unroll
            for (int s = 0; s < 8; s++) {
                int bb = min(s0 + s, B - 1);
                bs[s] = bb;
                step[s] = (__ldg(&labels[bb]) >> 10) & 31;
                if (s0 + s < B) msk |= 1u << s;
            }
            process_run_smem(x, wps, bs, msk, step, lane, xsm, g_p);
        } else {
            // level 1: node k; twin CTA takes even/odd tiles of sorted range
            int half = (c - 192) & 1;
            int beg = __ldg(&g_off[k * 32]);
            int end = __ldg(&g_off[k * 32 + 32]);
            int ntiles = (end - beg + 7) >> 3;
            #pragma unroll 1
            for (int t = 2 * wid + half; t < ntiles; t += 16) {
                int t0 = beg + t * 8;
                int G = min(8, end - t0);
                int bs[8], step[8];
                #pragma unroll
                for (int s = 0; s < 8; s++) {
                    int idx = t0 + ((s < G) ? s : (G - 1));
                    int bb = __ldg(&g_sorted[idx]);
                    bs[s] = bb;
                    step[s] = (__ldg(&labels[bb]) >> 5) & 31;
                }
                unsigned msk = (G >= 8) ? 0xffu : ((1u << G) - 1u);
                process_run_smem(x, wps, bs, msk, step, lane, xsm, g_p + BTOT);
            }
        }
    }
}

__global__ void k_final(float* __restrict__ out, int B)
{
    int i = blockIdx.x * blockDim.x + threadIdx.x;
    if (i < B) out[i] = g_p[i] * g_p[BTOT + i] * g_p[2 * BTOT + i];
}

extern "C" void kernel_launch(void* const* d_in, const int* in_sizes, int n_in,
                              void* d_out, int out_size)
{
    const float* x      = (const float*)d_in[0];
    const int*   labels = (const int*)d_in[1];
    const float* W      = (const float*)d_in[2];
    float* out = (float*)d_out;

    int B = in_sizes[1];  // 4096

    k_sort<<<1, NB2>>>(labels, B);

    cudaFuncSetAttribute(k_work, cudaFuncAttributeMaxDynamicSharedMemorySize,
                         DSMEM_BYTES);
    k_work<<<NCTA, 256, DSMEM_BYTES>>>(x, labels, W, B);

    k_final<<<(B + 255) / 256, 256>>>(out, B);
}